// round 1
// baseline (speedup 1.0000x reference)
#include <cuda_runtime.h>
#include <cuda_bf16.h>
#include <math.h>

// Problem constants
#define NB 8
#define LL 2048
#define NTOK (NB*LL)        // 16384
#define DD 1024
#define EE 8
#define HH 2048

// -------------------- device scratch (no allocs allowed) --------------------
__device__ float g_hidden[(size_t)NTOK * HH];   // 134 MB, permuted hidden activations
__device__ int   g_perm[NTOK];
__device__ int   g_topidx[NTOK];
__device__ float g_topw[NTOK];
__device__ int   g_counts[EE];
__device__ int   g_offs[EE + 1];
__device__ int   g_cursor[EE];

// -------------------- tiny setup kernels --------------------
__global__ void zero_kernel() {
    int t = threadIdx.x;
    if (t < EE) g_counts[t] = 0;
}

__global__ void scan_kernel() {
    int s = 0;
    g_offs[0] = 0;
    for (int e = 0; e < EE; e++) {
        g_cursor[e] = s;
        s += g_counts[e];
        g_offs[e + 1] = s;
    }
}

__global__ void scatter_kernel() {
    int t = blockIdx.x * blockDim.x + threadIdx.x;
    if (t < NTOK) {
        int e = g_topidx[t];
        int pos = atomicAdd(&g_cursor[e], 1);
        g_perm[pos] = t;
    }
}

// -------------------- gating: logits, softmax, argmax --------------------
// One warp per token. Each lane holds 32 of the 1024 x values in registers.
__global__ void gate_kernel(const float* __restrict__ x,
                            const float* __restrict__ Wg,
                            const float* __restrict__ bg,
                            float* __restrict__ gw_out) {
    int warp = threadIdx.x >> 5;
    int lane = threadIdx.x & 31;
    int t = blockIdx.x * 8 + warp;
    if (t >= NTOK) return;

    const float* xr = x + (size_t)t * DD;
    float xv[32];
#pragma unroll
    for (int i = 0; i < 32; i++) xv[i] = xr[lane + 32 * i];

    float logit[EE];
#pragma unroll
    for (int e = 0; e < EE; e++) {
        float s = 0.f;
#pragma unroll
        for (int i = 0; i < 32; i++) s += xv[i] * Wg[(lane + 32 * i) * EE + e];
#pragma unroll
        for (int o = 16; o > 0; o >>= 1) s += __shfl_xor_sync(0xffffffffu, s, o);
        logit[e] = s + bg[e];
    }

    if (lane == 0) {
        // argmax (first max, like jnp.argmax)
        float mx = logit[0]; int bi = 0;
#pragma unroll
        for (int e = 1; e < EE; e++) if (logit[e] > mx) { mx = logit[e]; bi = e; }
        float p[EE]; float se = 0.f;
#pragma unroll
        for (int e = 0; e < EE; e++) { p[e] = expf(logit[e] - mx); se += p[e]; }
        float inv = 1.f / se;
#pragma unroll
        for (int e = 0; e < EE; e++) gw_out[(size_t)t * EE + e] = p[e] * inv;
        g_topidx[t] = bi;
        g_topw[t]  = p[bi] * inv;
        atomicAdd(&g_counts[bi], 1);
    }
}

// -------------------- GEMM 1: hidden = relu(X_gathered @ W1[e] + b1[e]) -----
// 128x128 tile, BK=8, 256 threads, 8x8 microtile per thread.
__global__ __launch_bounds__(256, 1)
void ffn1_kernel(const float* __restrict__ x,
                 const float* __restrict__ W1,
                 const float* __restrict__ b1) {
    const int e   = blockIdx.z;
    const int base = g_offs[e];
    const int cnt  = g_offs[e + 1] - base;
    const int m0 = blockIdx.y * 128;
    if (m0 >= cnt) return;
    const int n0 = blockIdx.x * 128;
    const float* W = W1 + (size_t)e * DD * HH;

    __shared__ float As[8][128];
    __shared__ float Bs[8][128];
    __shared__ int   tok[128];

    const int tid = threadIdx.x;
    if (tid < 128) {
        int m = m0 + tid; if (m >= cnt) m = cnt - 1;
        tok[tid] = g_perm[base + m];
    }
    __syncthreads();

    const int arow = tid >> 1;             // 0..127
    const int acol = (tid & 1) << 2;       // 0 or 4
    const int bk   = tid >> 5;             // 0..7
    const int bn   = (tid & 31) << 2;      // 0..124
    const int tx   = tid & 15;
    const int ty   = tid >> 4;

    float acc[8][8];
#pragma unroll
    for (int i = 0; i < 8; i++)
#pragma unroll
        for (int j = 0; j < 8; j++) acc[i][j] = 0.f;

    const float* aptr = x + (size_t)tok[arow] * DD + acol;

    for (int k0 = 0; k0 < DD; k0 += 8) {
        float4 av = *(const float4*)(aptr + k0);
        float4 bv = *(const float4*)&W[(size_t)(k0 + bk) * HH + n0 + bn];
        As[acol + 0][arow] = av.x;
        As[acol + 1][arow] = av.y;
        As[acol + 2][arow] = av.z;
        As[acol + 3][arow] = av.w;
        *(float4*)&Bs[bk][bn] = bv;
        __syncthreads();
#pragma unroll
        for (int k = 0; k < 8; k++) {
            float a[8], b[8];
            *(float4*)(a)     = *(const float4*)&As[k][ty << 2];
            *(float4*)(a + 4) = *(const float4*)&As[k][64 + (ty << 2)];
            *(float4*)(b)     = *(const float4*)&Bs[k][tx << 2];
            *(float4*)(b + 4) = *(const float4*)&Bs[k][64 + (tx << 2)];
#pragma unroll
            for (int i = 0; i < 8; i++)
#pragma unroll
                for (int j = 0; j < 8; j++) acc[i][j] += a[i] * b[j];
        }
        __syncthreads();
    }

#pragma unroll
    for (int i = 0; i < 8; i++) {
        int r = (i < 4) ? (ty * 4 + i) : (64 + ty * 4 + (i - 4));
        int m = m0 + r;
        if (m >= cnt) continue;
        size_t p = (size_t)(base + m);
#pragma unroll
        for (int jh = 0; jh < 2; jh++) {
            int c = n0 + jh * 64 + tx * 4;
            const float* bb = b1 + e * HH + c;
            float4 v;
            v.x = fmaxf(acc[i][jh * 4 + 0] + bb[0], 0.f);
            v.y = fmaxf(acc[i][jh * 4 + 1] + bb[1], 0.f);
            v.z = fmaxf(acc[i][jh * 4 + 2] + bb[2], 0.f);
            v.w = fmaxf(acc[i][jh * 4 + 3] + bb[3], 0.f);
            *(float4*)&g_hidden[p * HH + c] = v;
        }
    }
}

// -------- GEMM 2: out[tok] = topw * (hidden @ W2[e] + b2[e]), scattered -----
__global__ __launch_bounds__(256, 1)
void ffn2_kernel(const float* __restrict__ W2,
                 const float* __restrict__ b2,
                 float* __restrict__ out) {
    const int e   = blockIdx.z;
    const int base = g_offs[e];
    const int cnt  = g_offs[e + 1] - base;
    const int m0 = blockIdx.y * 128;
    if (m0 >= cnt) return;
    const int n0 = blockIdx.x * 128;
    const float* W = W2 + (size_t)e * HH * DD;

    __shared__ float As[8][128];
    __shared__ float Bs[8][128];
    __shared__ int   tok[128];

    const int tid = threadIdx.x;
    if (tid < 128) {
        int m = m0 + tid; if (m >= cnt) m = cnt - 1;
        tok[tid] = g_perm[base + m];
    }
    __syncthreads();

    const int arow = tid >> 1;
    const int acol = (tid & 1) << 2;
    const int bk   = tid >> 5;
    const int bn   = (tid & 31) << 2;
    const int tx   = tid & 15;
    const int ty   = tid >> 4;

    float acc[8][8];
#pragma unroll
    for (int i = 0; i < 8; i++)
#pragma unroll
        for (int j = 0; j < 8; j++) acc[i][j] = 0.f;

    int mclamp = m0 + arow; if (mclamp >= cnt) mclamp = cnt - 1;
    const float* aptr = g_hidden + (size_t)(base + mclamp) * HH + acol;

    for (int k0 = 0; k0 < HH; k0 += 8) {
        float4 av = *(const float4*)(aptr + k0);
        float4 bv = *(const float4*)&W[(size_t)(k0 + bk) * DD + n0 + bn];
        As[acol + 0][arow] = av.x;
        As[acol + 1][arow] = av.y;
        As[acol + 2][arow] = av.z;
        As[acol + 3][arow] = av.w;
        *(float4*)&Bs[bk][bn] = bv;
        __syncthreads();
#pragma unroll
        for (int k = 0; k < 8; k++) {
            float a[8], b[8];
            *(float4*)(a)     = *(const float4*)&As[k][ty << 2];
            *(float4*)(a + 4) = *(const float4*)&As[k][64 + (ty << 2)];
            *(float4*)(b)     = *(const float4*)&Bs[k][tx << 2];
            *(float4*)(b + 4) = *(const float4*)&Bs[k][64 + (tx << 2)];
#pragma unroll
            for (int i = 0; i < 8; i++)
#pragma unroll
                for (int j = 0; j < 8; j++) acc[i][j] += a[i] * b[j];
        }
        __syncthreads();
    }

#pragma unroll
    for (int i = 0; i < 8; i++) {
        int r = (i < 4) ? (ty * 4 + i) : (64 + ty * 4 + (i - 4));
        int m = m0 + r;
        if (m >= cnt) continue;
        int t = tok[r];
        float w = g_topw[t];
#pragma unroll
        for (int jh = 0; jh < 2; jh++) {
            int c = n0 + jh * 64 + tx * 4;
            const float* bb = b2 + e * DD + c;
            float4 v;
            v.x = w * (acc[i][jh * 4 + 0] + bb[0]);
            v.y = w * (acc[i][jh * 4 + 1] + bb[1]);
            v.z = w * (acc[i][jh * 4 + 2] + bb[2]);
            v.w = w * (acc[i][jh * 4 + 3] + bb[3]);
            *(float4*)&out[(size_t)t * DD + c] = v;
        }
    }
}

// -------------------- launch --------------------
extern "C" void kernel_launch(void* const* d_in, const int* in_sizes, int n_in,
                              void* d_out, int out_size) {
    const float* x  = (const float*)d_in[0];
    const float* Wg = (const float*)d_in[1];
    const float* bg = (const float*)d_in[2];
    const float* W1 = (const float*)d_in[3];
    const float* b1 = (const float*)d_in[4];
    const float* W2 = (const float*)d_in[5];
    const float* b2 = (const float*)d_in[6];
    float* out = (float*)d_out;
    float* gw  = out + (size_t)NTOK * DD;   // gate_weights appended after `out`

    zero_kernel<<<1, 32>>>();
    gate_kernel<<<NTOK / 8, 256>>>(x, Wg, bg, gw);
    scan_kernel<<<1, 1>>>();
    scatter_kernel<<<NTOK / 256, 256>>>();
    ffn1_kernel<<<dim3(HH / 128, NTOK / 128, EE), 256>>>(x, W1, b1);
    ffn2_kernel<<<dim3(DD / 128, NTOK / 128, EE), 256>>>(W2, b2, out);
}

// round 3
// speedup vs baseline: 1.4593x; 1.4593x over previous
#include <cuda_runtime.h>
#include <cuda_bf16.h>
#include <math.h>
#include <stdint.h>

// Problem constants
#define NB 8
#define LL 2048
#define NTOK (NB*LL)        // 16384
#define DD 1024
#define EE 8
#define HH 2048

#define BM 128
#define BN 128
#define BK 32
#define NSTAGE 4
#define STAGE_BYTES 32768       // A tile 16KB + B tile 16KB
#define OFF_B 16384
#define OFF_TOK 0
#define OFF_TILE 1024
#define SMEM_TOTAL (OFF_TILE + NSTAGE * STAGE_BYTES)   // 132096

// -------------------- device scratch (no allocs allowed) --------------------
__device__ __nv_bfloat16 g_xhi[(size_t)NTOK * DD];
__device__ __nv_bfloat16 g_xlo[(size_t)NTOK * DD];
__device__ __nv_bfloat16 g_w1hi[(size_t)EE * HH * DD];   // [E][H][D]  (W1^T)
__device__ __nv_bfloat16 g_w1lo[(size_t)EE * HH * DD];
__device__ __nv_bfloat16 g_w2hi[(size_t)EE * DD * HH];   // [E][D][H]  (W2^T)
__device__ __nv_bfloat16 g_w2lo[(size_t)EE * DD * HH];
__device__ __nv_bfloat16 g_hhi[(size_t)NTOK * HH];       // permuted hidden (hi)
__device__ __nv_bfloat16 g_hlo[(size_t)NTOK * HH];       // permuted hidden (lo)
__device__ int   g_perm[NTOK];
__device__ int   g_topidx[NTOK];
__device__ float g_topw[NTOK];
__device__ int   g_counts[EE];
__device__ int   g_offs[EE + 1];
__device__ int   g_cursor[EE];

// -------------------- PTX helpers (all non-'a' features) --------------------
__device__ __forceinline__ uint32_t smem_u32(const void* p) {
    uint32_t a;
    asm("{ .reg .u64 t; cvta.to.shared.u64 t, %1; cvt.u32.u64 %0, t; }" : "=r"(a) : "l"(p));
    return a;
}
__device__ __forceinline__ void cp16(uint32_t dst, const void* src) {
    asm volatile("cp.async.cg.shared.global [%0], [%1], 16;" :: "r"(dst), "l"(src));
}
#define CP_COMMIT() asm volatile("cp.async.commit_group;" ::: "memory")
#define CP_WAIT(n)  asm volatile("cp.async.wait_group %0;" :: "n"(n) : "memory")

__device__ __forceinline__ void ldsm4(uint32_t* r, uint32_t addr) {
    asm volatile("ldmatrix.sync.aligned.m8n8.x4.shared.b16 {%0,%1,%2,%3}, [%4];"
                 : "=r"(r[0]), "=r"(r[1]), "=r"(r[2]), "=r"(r[3]) : "r"(addr));
}
__device__ __forceinline__ void mma16816(float* c, const uint32_t* a, const uint32_t* b) {
    asm volatile("mma.sync.aligned.m16n8k16.row.col.f32.bf16.bf16.f32 "
        "{%0,%1,%2,%3}, {%4,%5,%6,%7}, {%8,%9}, {%0,%1,%2,%3};"
        : "+f"(c[0]), "+f"(c[1]), "+f"(c[2]), "+f"(c[3])
        : "r"(a[0]), "r"(a[1]), "r"(a[2]), "r"(a[3]), "r"(b[0]), "r"(b[1]));
}

// -------------------- conversion kernels --------------------
__global__ void convx_kernel(const float* __restrict__ x) {
    size_t i = (size_t)blockIdx.x * blockDim.x + threadIdx.x;
    if (i < EE) g_counts[i] = 0;
    float4 v = ((const float4*)x)[i];
    __nv_bfloat16 h0 = __float2bfloat16(v.x), h1 = __float2bfloat16(v.y);
    __nv_bfloat16 h2 = __float2bfloat16(v.z), h3 = __float2bfloat16(v.w);
    __nv_bfloat16 l0 = __float2bfloat16(v.x - __bfloat162float(h0));
    __nv_bfloat16 l1 = __float2bfloat16(v.y - __bfloat162float(h1));
    __nv_bfloat16 l2 = __float2bfloat16(v.z - __bfloat162float(h2));
    __nv_bfloat16 l3 = __float2bfloat16(v.w - __bfloat162float(h3));
    __nv_bfloat162* ph = (__nv_bfloat162*)g_xhi;
    __nv_bfloat162* pl = (__nv_bfloat162*)g_xlo;
    __nv_bfloat162 a; a.x = h0; a.y = h1; ph[i * 2] = a;
    __nv_bfloat162 b; b.x = h2; b.y = h3; ph[i * 2 + 1] = b;
    __nv_bfloat162 c; c.x = l0; c.y = l1; pl[i * 2] = c;
    __nv_bfloat162 d; d.x = l2; d.y = l3; pl[i * 2 + 1] = d;
}

__global__ void convw_kernel(const float* __restrict__ W1, const float* __restrict__ W2) {
    int z = blockIdx.z;
    const float* src;
    __nv_bfloat16 *dh, *dl;
    int K, N;
    if (z < EE) {
        src = W1 + (size_t)z * DD * HH; dh = g_w1hi + (size_t)z * HH * DD;
        dl = g_w1lo + (size_t)z * HH * DD; K = DD; N = HH;
        if ((int)blockIdx.y >= K / 32) return;
    } else {
        int e = z - EE;
        src = W2 + (size_t)e * HH * DD; dh = g_w2hi + (size_t)e * DD * HH;
        dl = g_w2lo + (size_t)e * DD * HH; K = HH; N = DD;
        if ((int)blockIdx.x >= N / 32) return;
    }
    __shared__ float t[32][33];
    int tx = threadIdx.x, ty = threadIdx.y;
    int n0 = blockIdx.x * 32, k0 = blockIdx.y * 32;
#pragma unroll
    for (int i = 0; i < 4; i++)
        t[ty + i * 8][tx] = src[(size_t)(k0 + ty + i * 8) * N + n0 + tx];
    __syncthreads();
#pragma unroll
    for (int i = 0; i < 4; i++) {
        float v = t[tx][ty + i * 8];
        size_t o = (size_t)(n0 + ty + i * 8) * K + (k0 + tx);
        __nv_bfloat16 h = __float2bfloat16(v);
        dh[o] = h;
        dl[o] = __float2bfloat16(v - __bfloat162float(h));
    }
}

__global__ void scan_kernel() {
    int s = 0;
    g_offs[0] = 0;
    for (int e = 0; e < EE; e++) {
        g_cursor[e] = s;
        s += g_counts[e];
        g_offs[e + 1] = s;
    }
}

__global__ void scatter_kernel() {
    int t = blockIdx.x * blockDim.x + threadIdx.x;
    if (t < NTOK) {
        int e = g_topidx[t];
        int pos = atomicAdd(&g_cursor[e], 1);
        g_perm[pos] = t;
    }
}

// -------------------- gating --------------------
__global__ void gate_kernel(const float* __restrict__ x,
                            const float* __restrict__ Wg,
                            const float* __restrict__ bg,
                            float* __restrict__ gw_out) {
    int warp = threadIdx.x >> 5;
    int lane = threadIdx.x & 31;
    int t = blockIdx.x * 8 + warp;
    if (t >= NTOK) return;

    const float* xr = x + (size_t)t * DD;
    float xv[32];
#pragma unroll
    for (int i = 0; i < 32; i++) xv[i] = xr[lane + 32 * i];

    float logit[EE];
#pragma unroll
    for (int e = 0; e < EE; e++) {
        float s = 0.f;
#pragma unroll
        for (int i = 0; i < 32; i++) s += xv[i] * Wg[(lane + 32 * i) * EE + e];
#pragma unroll
        for (int o = 16; o > 0; o >>= 1) s += __shfl_xor_sync(0xffffffffu, s, o);
        logit[e] = s + bg[e];
    }

    if (lane == 0) {
        float mx = logit[0]; int bi = 0;
#pragma unroll
        for (int e = 1; e < EE; e++) if (logit[e] > mx) { mx = logit[e]; bi = e; }
        float p[EE]; float se = 0.f;
#pragma unroll
        for (int e = 0; e < EE; e++) { p[e] = expf(logit[e] - mx); se += p[e]; }
        float inv = 1.f / se;
#pragma unroll
        for (int e = 0; e < EE; e++) gw_out[(size_t)t * EE + e] = p[e] * inv;
        g_topidx[t] = bi;
        g_topw[t]  = p[bi] * inv;
        atomicAdd(&g_counts[bi], 1);
    }
}

// -------------------- mma.sync MoE GEMM --------------------
// SMEM tile row layout (A and B, 128 rows each): 128B/row = [hi 32 bf16 | lo 32 bf16],
// 16B chunks swizzled: chunk' = chunk ^ (row & 7)  -> conflict-free ldmatrix + stores.
// 3-term Markidis: C += Ah*Bh + Ah*Bl + Al*Bh  (fp32 accum, err ~2^-16).
#define LOAD_STAGE(c) do { \
    uint32_t db = dstbase + ((c) & (NSTAGE - 1)) * STAGE_BYTES; \
    const __nv_bfloat16* sh = srchi + (size_t)(c) * BK; \
    const __nv_bfloat16* sl = srclo + (size_t)(c) * BK; \
    cp16(db + ((0u ^ swr) << 4), sh + 0);  cp16(db + ((1u ^ swr) << 4), sh + 8); \
    cp16(db + ((2u ^ swr) << 4), sh + 16); cp16(db + ((3u ^ swr) << 4), sh + 24); \
    cp16(db + ((4u ^ swr) << 4), sl + 0);  cp16(db + ((5u ^ swr) << 4), sl + 8); \
    cp16(db + ((6u ^ swr) << 4), sl + 16); cp16(db + ((7u ^ swr) << 4), sl + 24); \
} while (0)

template<int MODE>
__global__ __launch_bounds__(256, 1)
void moe_gemm(const float* __restrict__ bias, float* __restrict__ out) {
    constexpr int KTOT = (MODE == 0) ? DD : HH;
    constexpr int NROW = (MODE == 0) ? HH : DD;
    constexpr int NCH  = KTOT / BK;       // 32 or 64

    const int e    = blockIdx.z;
    const int base = g_offs[e];
    const int cnt  = g_offs[e + 1] - base;
    const int m0   = blockIdx.y * BM;
    if (m0 >= cnt) return;
    const int n0   = blockIdx.x * BN;

    extern __shared__ char smem[];
    const uint32_t S = smem_u32(smem);
    int* tok = (int*)(smem + OFF_TOK);
    const int tid = threadIdx.x;

    if (tid < 128) {
        int m = m0 + tid; if (m >= cnt) m = cnt - 1;
        tok[tid] = g_perm[base + m];
    }
    __syncthreads();

    // ---- async loader setup: tid<128 -> A row tid, tid>=128 -> B row tid-128 ----
    const int lr = tid & 127;
    const bool isB = tid >= 128;
    const __nv_bfloat16 *srchi, *srclo;
    if (!isB) {
        size_t row;
        if (MODE == 0) row = (size_t)tok[lr];
        else { int m = m0 + lr; if (m >= cnt) m = cnt - 1; row = (size_t)(base + m); }
        srchi = ((MODE == 0) ? g_xhi : g_hhi) + row * KTOT;
        srclo = ((MODE == 0) ? g_xlo : g_hlo) + row * KTOT;
    } else {
        size_t row = (size_t)e * NROW + n0 + lr;
        srchi = ((MODE == 0) ? g_w1hi : g_w2hi) + row * KTOT;
        srclo = ((MODE == 0) ? g_w1lo : g_w2lo) + row * KTOT;
    }
    const uint32_t dstbase = S + OFF_TILE + (isB ? OFF_B : 0) + (uint32_t)lr * 128;
    const uint32_t swr = (uint32_t)(lr & 7);

    // ---- fragment addressing ----
    const int lane = tid & 31, wid = tid >> 5;
    const int wm = wid >> 2, wn = wid & 3;          // warp tile: rows wm*64, cols wn*32
    const uint32_t rA   = lane & 15;
    const uint32_t cA   = lane >> 4;                // +0/+1 chunk
    const uint32_t swA  = rA & 7;
    uint32_t rowA[4];
#pragma unroll
    for (int i = 0; i < 4; i++) rowA[i] = (uint32_t)(wm * 64 + i * 16 + rA) * 128;
    const uint32_t rB   = (lane & 7) | ((lane >> 1) & 8);   // +8 for lanes 16..31
    const uint32_t cB   = (lane >> 3) & 1;
    const uint32_t swB  = rB & 7;
    uint32_t rowB[2];
#pragma unroll
    for (int jj = 0; jj < 2; jj++) rowB[jj] = (uint32_t)(wn * 32 + jj * 16 + rB) * 128;

    float C[4][4][4];
#pragma unroll
    for (int i = 0; i < 4; i++)
#pragma unroll
        for (int j = 0; j < 4; j++)
#pragma unroll
            for (int q = 0; q < 4; q++) C[i][j][q] = 0.f;

    LOAD_STAGE(0); CP_COMMIT();
    LOAD_STAGE(1); CP_COMMIT();
    LOAD_STAGE(2); CP_COMMIT();

    for (int c = 0; c < NCH; c++) {
        if (c + 3 < NCH) LOAD_STAGE(c + 3);
        CP_COMMIT();
        CP_WAIT(3);
        __syncthreads();
        const uint32_t aBuf = S + OFF_TILE + (uint32_t)(c & (NSTAGE - 1)) * STAGE_BYTES;
        const uint32_t bBuf = aBuf + OFF_B;
#pragma unroll
        for (int s = 0; s < 2; s++) {
            const uint32_t kch = 2 * s;        // hi chunks 0..3
            const uint32_t kcl = 4 + 2 * s;    // lo chunks 4..7
            uint32_t Ah[4][4], Al[4][4], Bh[2][4], Bl[2][4];
#pragma unroll
            for (int i = 0; i < 4; i++) {
                ldsm4(Ah[i], aBuf + rowA[i] + (((kch + cA) ^ swA) << 4));
                ldsm4(Al[i], aBuf + rowA[i] + (((kcl + cA) ^ swA) << 4));
            }
#pragma unroll
            for (int jj = 0; jj < 2; jj++) {
                ldsm4(Bh[jj], bBuf + rowB[jj] + (((kch + cB) ^ swB) << 4));
                ldsm4(Bl[jj], bBuf + rowB[jj] + (((kcl + cB) ^ swB) << 4));
            }
            // term-major for ILP: hi*hi, hi*lo, lo*hi
#pragma unroll
            for (int i = 0; i < 4; i++)
#pragma unroll
                for (int j = 0; j < 4; j++)
                    mma16816(C[i][j], Ah[i], &Bh[j >> 1][(j & 1) * 2]);
#pragma unroll
            for (int i = 0; i < 4; i++)
#pragma unroll
                for (int j = 0; j < 4; j++)
                    mma16816(C[i][j], Ah[i], &Bl[j >> 1][(j & 1) * 2]);
#pragma unroll
            for (int i = 0; i < 4; i++)
#pragma unroll
                for (int j = 0; j < 4; j++)
                    mma16816(C[i][j], Al[i], &Bh[j >> 1][(j & 1) * 2]);
        }
        __syncthreads();
    }

    // -------- epilogue --------
    const int gcol0 = n0 + wn * 32;
#pragma unroll
    for (int i = 0; i < 4; i++) {
        const int rbase = wm * 64 + i * 16 + (lane >> 2);
#pragma unroll
        for (int half = 0; half < 2; half++) {
            const int rr = rbase + 8 * half;
            const int m  = m0 + rr;
            if (m >= cnt) continue;
            if (MODE == 0) {
                const size_t pb = (size_t)(base + m) * HH;
#pragma unroll
                for (int j = 0; j < 4; j++) {
                    const int cc = gcol0 + j * 8 + (lane & 3) * 2;
                    float v0 = fmaxf(C[i][j][2 * half]     + bias[e * HH + cc],     0.f);
                    float v1 = fmaxf(C[i][j][2 * half + 1] + bias[e * HH + cc + 1], 0.f);
                    __nv_bfloat16 h0 = __float2bfloat16(v0), h1 = __float2bfloat16(v1);
                    __nv_bfloat162 hp; hp.x = h0; hp.y = h1;
                    __nv_bfloat162 lp;
                    lp.x = __float2bfloat16(v0 - __bfloat162float(h0));
                    lp.y = __float2bfloat16(v1 - __bfloat162float(h1));
                    *(__nv_bfloat162*)(&g_hhi[pb + cc]) = hp;
                    *(__nv_bfloat162*)(&g_hlo[pb + cc]) = lp;
                }
            } else {
                const int t = tok[rr];
                const float w = g_topw[t];
                float* op = out + (size_t)t * DD;
#pragma unroll
                for (int j = 0; j < 4; j++) {
                    const int cc = gcol0 + j * 8 + (lane & 3) * 2;
                    float2 v;
                    v.x = w * (C[i][j][2 * half]     + bias[e * DD + cc]);
                    v.y = w * (C[i][j][2 * half + 1] + bias[e * DD + cc + 1]);
                    *(float2*)(op + cc) = v;
                }
            }
        }
    }
}

// -------------------- launch --------------------
extern "C" void kernel_launch(void* const* d_in, const int* in_sizes, int n_in,
                              void* d_out, int out_size) {
    const float* x  = (const float*)d_in[0];
    const float* Wg = (const float*)d_in[1];
    const float* bg = (const float*)d_in[2];
    const float* W1 = (const float*)d_in[3];
    const float* b1 = (const float*)d_in[4];
    const float* W2 = (const float*)d_in[5];
    const float* b2 = (const float*)d_in[6];
    float* out = (float*)d_out;
    float* gw  = out + (size_t)NTOK * DD;   // gate_weights appended after `out`

    cudaFuncSetAttribute(moe_gemm<0>, cudaFuncAttributeMaxDynamicSharedMemorySize, SMEM_TOTAL);
    cudaFuncSetAttribute(moe_gemm<1>, cudaFuncAttributeMaxDynamicSharedMemorySize, SMEM_TOTAL);

    convx_kernel<<<(NTOK * DD / 4) / 256, 256>>>(x);          // 0 (also zeros counts)
    gate_kernel<<<NTOK / 8, 256>>>(x, Wg, bg, gw);            // 1
    scan_kernel<<<1, 1>>>();                                  // 2
    scatter_kernel<<<NTOK / 256, 256>>>();                    // 3
    convw_kernel<<<dim3(64, 64, 16), dim3(32, 8)>>>(W1, W2);  // 4
    moe_gemm<0><<<dim3(HH / BN, NTOK / BM, EE), 256, SMEM_TOTAL>>>(b1, nullptr);  // 5 (ncu)
    moe_gemm<1><<<dim3(DD / BN, NTOK / BM, EE), 256, SMEM_TOTAL>>>(b2, out);      // 6
}

// round 4
// speedup vs baseline: 2.8260x; 1.9365x over previous
#include <cuda_runtime.h>
#include <cuda_fp16.h>
#include <math.h>
#include <stdint.h>

// Problem constants
#define NB 8
#define LL 2048
#define NTOK (NB*LL)        // 16384
#define DD 1024
#define EE 8
#define HH 2048

#define BM 128
#define BN 128
#define BK 64
#define NSTAGE 4
#define STAGE_BYTES 32768       // A tile 16KB + B tile 16KB
#define OFF_B 16384
#define OFF_TOK 0
#define OFF_TILE 1024
#define SMEM_TOTAL (OFF_TILE + NSTAGE * STAGE_BYTES)   // 132096

// -------------------- device scratch (no allocs allowed) --------------------
__device__ __half g_xh[(size_t)NTOK * DD];
__device__ __half g_w1h[(size_t)EE * HH * DD];   // [E][H][D]  (W1^T)
__device__ __half g_w2h[(size_t)EE * DD * HH];   // [E][D][H]  (W2^T)
__device__ __half g_h[(size_t)NTOK * HH];        // permuted hidden
__device__ int   g_perm[NTOK];
__device__ int   g_topidx[NTOK];
__device__ float g_topw[NTOK];
__device__ int   g_counts[EE];
__device__ int   g_offs[EE + 1];
__device__ int   g_cursor[EE];

// -------------------- PTX helpers (all non-'a' features) --------------------
__device__ __forceinline__ uint32_t smem_u32(const void* p) {
    uint32_t a;
    asm("{ .reg .u64 t; cvta.to.shared.u64 t, %1; cvt.u32.u64 %0, t; }" : "=r"(a) : "l"(p));
    return a;
}
__device__ __forceinline__ void cp16(uint32_t dst, const void* src) {
    asm volatile("cp.async.cg.shared.global [%0], [%1], 16;" :: "r"(dst), "l"(src));
}
#define CP_COMMIT() asm volatile("cp.async.commit_group;" ::: "memory")
#define CP_WAIT(n)  asm volatile("cp.async.wait_group %0;" :: "n"(n) : "memory")

__device__ __forceinline__ void ldsm4(uint32_t* r, uint32_t addr) {
    asm volatile("ldmatrix.sync.aligned.m8n8.x4.shared.b16 {%0,%1,%2,%3}, [%4];"
                 : "=r"(r[0]), "=r"(r[1]), "=r"(r[2]), "=r"(r[3]) : "r"(addr));
}
__device__ __forceinline__ void mma16816(float* c, const uint32_t* a, const uint32_t* b) {
    asm volatile("mma.sync.aligned.m16n8k16.row.col.f32.f16.f16.f32 "
        "{%0,%1,%2,%3}, {%4,%5,%6,%7}, {%8,%9}, {%0,%1,%2,%3};"
        : "+f"(c[0]), "+f"(c[1]), "+f"(c[2]), "+f"(c[3])
        : "r"(a[0]), "r"(a[1]), "r"(a[2]), "r"(a[3]), "r"(b[0]), "r"(b[1]));
}

// -------------------- conversion kernels --------------------
__global__ void convx_kernel(const float* __restrict__ x) {
    size_t i = (size_t)blockIdx.x * blockDim.x + threadIdx.x;
    if (i < EE) g_counts[i] = 0;
    float4 v = ((const float4*)x)[i];
    __half2* ph = (__half2*)g_xh;
    ph[i * 2]     = __floats2half2_rn(v.x, v.y);
    ph[i * 2 + 1] = __floats2half2_rn(v.z, v.w);
}

__global__ void convw_kernel(const float* __restrict__ W1, const float* __restrict__ W2) {
    int z = blockIdx.z;
    const float* src;
    __half* dh;
    int K, N;
    if (z < EE) {
        src = W1 + (size_t)z * DD * HH; dh = g_w1h + (size_t)z * HH * DD;
        K = DD; N = HH;
        if ((int)blockIdx.y >= K / 32) return;
    } else {
        int e = z - EE;
        src = W2 + (size_t)e * HH * DD; dh = g_w2h + (size_t)e * DD * HH;
        K = HH; N = DD;
        if ((int)blockIdx.x >= N / 32) return;
    }
    __shared__ float t[32][33];
    int tx = threadIdx.x, ty = threadIdx.y;
    int n0 = blockIdx.x * 32, k0 = blockIdx.y * 32;
#pragma unroll
    for (int i = 0; i < 4; i++)
        t[ty + i * 8][tx] = src[(size_t)(k0 + ty + i * 8) * N + n0 + tx];
    __syncthreads();
#pragma unroll
    for (int i = 0; i < 4; i++) {
        float v = t[tx][ty + i * 8];
        size_t o = (size_t)(n0 + ty + i * 8) * K + (k0 + tx);
        dh[o] = __float2half_rn(v);
    }
}

__global__ void scan_kernel() {
    int s = 0;
    g_offs[0] = 0;
    for (int e = 0; e < EE; e++) {
        g_cursor[e] = s;
        s += g_counts[e];
        g_offs[e + 1] = s;
    }
}

__global__ void scatter_kernel() {
    int t = blockIdx.x * blockDim.x + threadIdx.x;
    if (t < NTOK) {
        int e = g_topidx[t];
        int pos = atomicAdd(&g_cursor[e], 1);
        g_perm[pos] = t;
    }
}

// -------------------- gating --------------------
__global__ void gate_kernel(const float* __restrict__ x,
                            const float* __restrict__ Wg,
                            const float* __restrict__ bg,
                            float* __restrict__ gw_out) {
    int warp = threadIdx.x >> 5;
    int lane = threadIdx.x & 31;
    int t = blockIdx.x * 8 + warp;
    if (t >= NTOK) return;

    const float* xr = x + (size_t)t * DD;
    float xv[32];
#pragma unroll
    for (int i = 0; i < 32; i++) xv[i] = xr[lane + 32 * i];

    float logit[EE];
#pragma unroll
    for (int e = 0; e < EE; e++) {
        float s = 0.f;
#pragma unroll
        for (int i = 0; i < 32; i++) s += xv[i] * Wg[(lane + 32 * i) * EE + e];
#pragma unroll
        for (int o = 16; o > 0; o >>= 1) s += __shfl_xor_sync(0xffffffffu, s, o);
        logit[e] = s + bg[e];
    }

    if (lane == 0) {
        float mx = logit[0]; int bi = 0;
#pragma unroll
        for (int e = 1; e < EE; e++) if (logit[e] > mx) { mx = logit[e]; bi = e; }
        float p[EE]; float se = 0.f;
#pragma unroll
        for (int e = 0; e < EE; e++) { p[e] = expf(logit[e] - mx); se += p[e]; }
        float inv = 1.f / se;
#pragma unroll
        for (int e = 0; e < EE; e++) gw_out[(size_t)t * EE + e] = p[e] * inv;
        g_topidx[t] = bi;
        g_topw[t]  = p[bi] * inv;
        atomicAdd(&g_counts[bi], 1);
    }
}

// -------------------- mma.sync MoE GEMM (fp16, 1-term) --------------------
// SMEM tile row layout (A and B, 128 rows each): 128B/row = 64 fp16 (k-dim),
// 16B chunks swizzled: chunk' = chunk ^ (row & 7)  -> conflict-free ldmatrix + cp.async.
#define LOAD_STAGE(c) do { \
    uint32_t db = dstbase + ((c) & (NSTAGE - 1)) * STAGE_BYTES; \
    const __half* sp = srcp + (size_t)(c) * BK; \
    cp16(db + ((0u ^ swr) << 4), sp + 0);  cp16(db + ((1u ^ swr) << 4), sp + 8); \
    cp16(db + ((2u ^ swr) << 4), sp + 16); cp16(db + ((3u ^ swr) << 4), sp + 24); \
    cp16(db + ((4u ^ swr) << 4), sp + 32); cp16(db + ((5u ^ swr) << 4), sp + 40); \
    cp16(db + ((6u ^ swr) << 4), sp + 48); cp16(db + ((7u ^ swr) << 4), sp + 56); \
} while (0)

template<int MODE>
__global__ __launch_bounds__(256, 1)
void moe_gemm(const float* __restrict__ bias, float* __restrict__ out) {
    constexpr int KTOT = (MODE == 0) ? DD : HH;
    constexpr int NROW = (MODE == 0) ? HH : DD;
    constexpr int NCH  = KTOT / BK;       // 16 or 32

    const int e    = blockIdx.z;
    const int base = g_offs[e];
    const int cnt  = g_offs[e + 1] - base;
    const int m0   = blockIdx.y * BM;
    if (m0 >= cnt) return;
    const int n0   = blockIdx.x * BN;

    extern __shared__ char smem[];
    const uint32_t S = smem_u32(smem);
    int* tok = (int*)(smem + OFF_TOK);
    const int tid = threadIdx.x;

    if (tid < 128) {
        int m = m0 + tid; if (m >= cnt) m = cnt - 1;
        tok[tid] = g_perm[base + m];
    }
    __syncthreads();

    // ---- async loader setup: tid<128 -> A row tid, tid>=128 -> B row tid-128 ----
    const int lr = tid & 127;
    const bool isB = tid >= 128;
    const __half* srcp;
    if (!isB) {
        size_t row;
        if (MODE == 0) row = (size_t)tok[lr];
        else { int m = m0 + lr; if (m >= cnt) m = cnt - 1; row = (size_t)(base + m); }
        srcp = ((MODE == 0) ? g_xh : g_h) + row * KTOT;
    } else {
        size_t row = (size_t)e * NROW + n0 + lr;
        srcp = ((MODE == 0) ? g_w1h : g_w2h) + row * KTOT;
    }
    const uint32_t dstbase = S + OFF_TILE + (isB ? OFF_B : 0) + (uint32_t)lr * 128;
    const uint32_t swr = (uint32_t)(lr & 7);

    // ---- fragment addressing ----
    const int lane = tid & 31, wid = tid >> 5;
    const int wm = wid >> 2, wn = wid & 3;          // warp tile: rows wm*64, cols wn*32
    const uint32_t rA   = lane & 15;
    const uint32_t cA   = lane >> 4;                // +0/+1 chunk
    const uint32_t swA  = rA & 7;
    uint32_t rowA[4];
#pragma unroll
    for (int i = 0; i < 4; i++) rowA[i] = (uint32_t)(wm * 64 + i * 16 + rA) * 128;
    const uint32_t rB   = (lane & 7) | ((lane >> 1) & 8);   // +8 for lanes 16..31
    const uint32_t cB   = (lane >> 3) & 1;
    const uint32_t swB  = rB & 7;
    uint32_t rowB[2];
#pragma unroll
    for (int jj = 0; jj < 2; jj++) rowB[jj] = (uint32_t)(wn * 32 + jj * 16 + rB) * 128;

    float C[4][4][4];
#pragma unroll
    for (int i = 0; i < 4; i++)
#pragma unroll
        for (int j = 0; j < 4; j++)
#pragma unroll
            for (int q = 0; q < 4; q++) C[i][j][q] = 0.f;

    LOAD_STAGE(0); CP_COMMIT();
    LOAD_STAGE(1); CP_COMMIT();
    LOAD_STAGE(2); CP_COMMIT();

    for (int c = 0; c < NCH; c++) {
        if (c + 3 < NCH) LOAD_STAGE(c + 3);
        CP_COMMIT();
        CP_WAIT(3);
        __syncthreads();
        const uint32_t aBuf = S + OFF_TILE + (uint32_t)(c & (NSTAGE - 1)) * STAGE_BYTES;
        const uint32_t bBuf = aBuf + OFF_B;
#pragma unroll
        for (int s = 0; s < 4; s++) {          // 4 x k16 per 64-chunk
            const uint32_t kc = 2 * s;
            uint32_t A[4][4], B[2][4];
#pragma unroll
            for (int i = 0; i < 4; i++)
                ldsm4(A[i], aBuf + rowA[i] + (((kc + cA) ^ swA) << 4));
#pragma unroll
            for (int jj = 0; jj < 2; jj++)
                ldsm4(B[jj], bBuf + rowB[jj] + (((kc + cB) ^ swB) << 4));
#pragma unroll
            for (int i = 0; i < 4; i++)
#pragma unroll
                for (int j = 0; j < 4; j++)
                    mma16816(C[i][j], A[i], &B[j >> 1][(j & 1) * 2]);
        }
        __syncthreads();
    }

    // -------- epilogue --------
    const int gcol0 = n0 + wn * 32;
#pragma unroll
    for (int i = 0; i < 4; i++) {
        const int rbase = wm * 64 + i * 16 + (lane >> 2);
#pragma unroll
        for (int half = 0; half < 2; half++) {
            const int rr = rbase + 8 * half;
            const int m  = m0 + rr;
            if (m >= cnt) continue;
            if (MODE == 0) {
                const size_t pb = (size_t)(base + m) * HH;
#pragma unroll
                for (int j = 0; j < 4; j++) {
                    const int cc = gcol0 + j * 8 + (lane & 3) * 2;
                    float v0 = fmaxf(C[i][j][2 * half]     + bias[e * HH + cc],     0.f);
                    float v1 = fmaxf(C[i][j][2 * half + 1] + bias[e * HH + cc + 1], 0.f);
                    *(__half2*)(&g_h[pb + cc]) = __floats2half2_rn(v0, v1);
                }
            } else {
                const int t = tok[rr];
                const float w = g_topw[t];
                float* op = out + (size_t)t * DD;
#pragma unroll
                for (int j = 0; j < 4; j++) {
                    const int cc = gcol0 + j * 8 + (lane & 3) * 2;
                    float2 v;
                    v.x = w * (C[i][j][2 * half]     + bias[e * DD + cc]);
                    v.y = w * (C[i][j][2 * half + 1] + bias[e * DD + cc + 1]);
                    *(float2*)(op + cc) = v;
                }
            }
        }
    }
}

// -------------------- launch --------------------
extern "C" void kernel_launch(void* const* d_in, const int* in_sizes, int n_in,
                              void* d_out, int out_size) {
    const float* x  = (const float*)d_in[0];
    const float* Wg = (const float*)d_in[1];
    const float* bg = (const float*)d_in[2];
    const float* W1 = (const float*)d_in[3];
    const float* b1 = (const float*)d_in[4];
    const float* W2 = (const float*)d_in[5];
    const float* b2 = (const float*)d_in[6];
    float* out = (float*)d_out;
    float* gw  = out + (size_t)NTOK * DD;   // gate_weights appended after `out`

    cudaFuncSetAttribute(moe_gemm<0>, cudaFuncAttributeMaxDynamicSharedMemorySize, SMEM_TOTAL);
    cudaFuncSetAttribute(moe_gemm<1>, cudaFuncAttributeMaxDynamicSharedMemorySize, SMEM_TOTAL);

    convx_kernel<<<(NTOK * DD / 4) / 256, 256>>>(x);          // 0 (also zeros counts)
    gate_kernel<<<NTOK / 8, 256>>>(x, Wg, bg, gw);            // 1
    scan_kernel<<<1, 1>>>();                                  // 2
    scatter_kernel<<<NTOK / 256, 256>>>();                    // 3
    convw_kernel<<<dim3(64, 64, 16), dim3(32, 8)>>>(W1, W2);  // 4
    moe_gemm<0><<<dim3(HH / BN, NTOK / BM, EE), 256, SMEM_TOTAL>>>(b1, nullptr);  // 5
    moe_gemm<1><<<dim3(DD / BN, NTOK / BM, EE), 256, SMEM_TOTAL>>>(b2, out);      // 6
}

// round 5
// speedup vs baseline: 3.3507x; 1.1857x over previous
#include <cuda_runtime.h>
#include <cuda_fp16.h>
#include <math.h>
#include <stdint.h>

// Problem constants
#define NB 8
#define LL 2048
#define NTOK (NB*LL)        // 16384
#define DD 1024
#define EE 8
#define HH 2048

#define BM 128
#define BN 128
#define BK 64
#define NSTAGE 3
#define STAGE_BYTES 32768       // A tile 16KB + B tile 16KB
#define OFF_B 16384
#define OFF_TOK 0
#define OFF_TILE 1024
#define SMEM_TOTAL (OFF_TILE + NSTAGE * STAGE_BYTES)   // 99328

// -------------------- device scratch (no allocs allowed) --------------------
__device__ __half g_xh[(size_t)NTOK * DD];
__device__ __half g_w1h[(size_t)EE * HH * DD];   // [E][H][D]  (W1^T)
__device__ __half g_w2h[(size_t)EE * DD * HH];   // [E][D][H]  (W2^T)
__device__ __half g_h[(size_t)NTOK * HH];        // permuted hidden
__device__ int   g_perm[NTOK];
__device__ int   g_topidx[NTOK];
__device__ float g_topw[NTOK];
__device__ int   g_counts[EE];
__device__ int   g_offs[EE + 1];
__device__ int   g_cursor[EE];

// -------------------- PTX helpers (all non-'a' features) --------------------
__device__ __forceinline__ uint32_t smem_u32(const void* p) {
    uint32_t a;
    asm("{ .reg .u64 t; cvta.to.shared.u64 t, %1; cvt.u32.u64 %0, t; }" : "=r"(a) : "l"(p));
    return a;
}
__device__ __forceinline__ void cp16(uint32_t dst, const void* src) {
    asm volatile("cp.async.cg.shared.global [%0], [%1], 16;" :: "r"(dst), "l"(src));
}
#define CP_COMMIT() asm volatile("cp.async.commit_group;" ::: "memory")
#define CP_WAIT(n)  asm volatile("cp.async.wait_group %0;" :: "n"(n) : "memory")

__device__ __forceinline__ void ldsm4(uint32_t* r, uint32_t addr) {
    asm volatile("ldmatrix.sync.aligned.m8n8.x4.shared.b16 {%0,%1,%2,%3}, [%4];"
                 : "=r"(r[0]), "=r"(r[1]), "=r"(r[2]), "=r"(r[3]) : "r"(addr));
}
__device__ __forceinline__ void mma16816(float* c, const uint32_t* a, const uint32_t* b) {
    asm volatile("mma.sync.aligned.m16n8k16.row.col.f32.f16.f16.f32 "
        "{%0,%1,%2,%3}, {%4,%5,%6,%7}, {%8,%9}, {%0,%1,%2,%3};"
        : "+f"(c[0]), "+f"(c[1]), "+f"(c[2]), "+f"(c[3])
        : "r"(a[0]), "r"(a[1]), "r"(a[2]), "r"(a[3]), "r"(b[0]), "r"(b[1]));
}

// -------------------- setup kernels --------------------
__global__ void zero_kernel() {
    int t = threadIdx.x;
    if (t < EE) g_counts[t] = 0;
}

__global__ void convw_kernel(const float* __restrict__ W1, const float* __restrict__ W2) {
    int z = blockIdx.z;
    const float* src;
    __half* dh;
    int K, N;
    if (z < EE) {
        src = W1 + (size_t)z * DD * HH; dh = g_w1h + (size_t)z * HH * DD;
        K = DD; N = HH;
        if ((int)blockIdx.y >= K / 32) return;
    } else {
        int e = z - EE;
        src = W2 + (size_t)e * HH * DD; dh = g_w2h + (size_t)e * DD * HH;
        K = HH; N = DD;
        if ((int)blockIdx.x >= N / 32) return;
    }
    __shared__ float t[32][33];
    int tx = threadIdx.x, ty = threadIdx.y;
    int n0 = blockIdx.x * 32, k0 = blockIdx.y * 32;
#pragma unroll
    for (int i = 0; i < 4; i++)
        t[ty + i * 8][tx] = src[(size_t)(k0 + ty + i * 8) * N + n0 + tx];
    __syncthreads();
#pragma unroll
    for (int i = 0; i < 4; i++) {
        float v = t[tx][ty + i * 8];
        size_t o = (size_t)(n0 + ty + i * 8) * K + (k0 + tx);
        dh[o] = __float2half_rn(v);
    }
}

__global__ void scan_kernel() {
    int s = 0;
    g_offs[0] = 0;
    for (int e = 0; e < EE; e++) {
        g_cursor[e] = s;
        s += g_counts[e];
        g_offs[e + 1] = s;
    }
}

__global__ void scatter_kernel() {
    int t = blockIdx.x * blockDim.x + threadIdx.x;
    if (t < NTOK) {
        int e = g_topidx[t];
        int pos = atomicAdd(&g_cursor[e], 1);
        g_perm[pos] = t;
    }
}

// -------------------- gating (fused with x->fp16 conversion) --------------------
__global__ void gate_kernel(const float* __restrict__ x,
                            const float* __restrict__ Wg,
                            const float* __restrict__ bg,
                            float* __restrict__ gw_out) {
    int warp = threadIdx.x >> 5;
    int lane = threadIdx.x & 31;
    int t = blockIdx.x * 8 + warp;
    if (t >= NTOK) return;

    const float* xr = x + (size_t)t * DD;
    float xv[32];
#pragma unroll
    for (int i = 0; i < 32; i++) xv[i] = xr[lane + 32 * i];

    // fused conversion: write fp16 copy of x
    __half* xh = g_xh + (size_t)t * DD;
#pragma unroll
    for (int i = 0; i < 32; i++) xh[lane + 32 * i] = __float2half_rn(xv[i]);

    float logit[EE];
#pragma unroll
    for (int e = 0; e < EE; e++) {
        float s = 0.f;
#pragma unroll
        for (int i = 0; i < 32; i++) s += xv[i] * Wg[(lane + 32 * i) * EE + e];
#pragma unroll
        for (int o = 16; o > 0; o >>= 1) s += __shfl_xor_sync(0xffffffffu, s, o);
        logit[e] = s + bg[e];
    }

    if (lane == 0) {
        float mx = logit[0]; int bi = 0;
#pragma unroll
        for (int e = 1; e < EE; e++) if (logit[e] > mx) { mx = logit[e]; bi = e; }
        float p[EE]; float se = 0.f;
#pragma unroll
        for (int e = 0; e < EE; e++) { p[e] = expf(logit[e] - mx); se += p[e]; }
        float inv = 1.f / se;
#pragma unroll
        for (int e = 0; e < EE; e++) gw_out[(size_t)t * EE + e] = p[e] * inv;
        g_topidx[t] = bi;
        g_topw[t]  = p[bi] * inv;
        atomicAdd(&g_counts[bi], 1);
    }
}

// -------------------- mma.sync MoE GEMM (fp16, 1-term) --------------------
// SMEM tile row layout (A and B, 128 rows each): 128B/row = 64 fp16 (k-dim),
// 16B chunks swizzled: chunk' = chunk ^ (row & 7)  -> conflict-free ldmatrix + cp.async.
#define LOAD_STAGE(c) do { \
    uint32_t db = dstbase + ((c) % NSTAGE) * STAGE_BYTES; \
    const __half* sp = srcp + (size_t)(c) * BK; \
    cp16(db + ((0u ^ swr) << 4), sp + 0);  cp16(db + ((1u ^ swr) << 4), sp + 8); \
    cp16(db + ((2u ^ swr) << 4), sp + 16); cp16(db + ((3u ^ swr) << 4), sp + 24); \
    cp16(db + ((4u ^ swr) << 4), sp + 32); cp16(db + ((5u ^ swr) << 4), sp + 40); \
    cp16(db + ((6u ^ swr) << 4), sp + 48); cp16(db + ((7u ^ swr) << 4), sp + 56); \
} while (0)

template<int MODE>
__global__ __launch_bounds__(256, 2)
void moe_gemm(const float* __restrict__ bias, float* __restrict__ out) {
    constexpr int KTOT = (MODE == 0) ? DD : HH;
    constexpr int NROW = (MODE == 0) ? HH : DD;
    constexpr int NCH  = KTOT / BK;       // 16 or 32

    const int e    = blockIdx.z;
    const int base = g_offs[e];
    const int cnt  = g_offs[e + 1] - base;
    const int m0   = blockIdx.y * BM;
    if (m0 >= cnt) return;
    const int n0   = blockIdx.x * BN;

    extern __shared__ char smem[];
    const uint32_t S = smem_u32(smem);
    int* tok = (int*)(smem + OFF_TOK);
    const int tid = threadIdx.x;

    if (tid < 128) {
        int m = m0 + tid; if (m >= cnt) m = cnt - 1;
        tok[tid] = g_perm[base + m];
    }
    __syncthreads();

    // ---- async loader setup: tid<128 -> A row tid, tid>=128 -> B row tid-128 ----
    const int lr = tid & 127;
    const bool isB = tid >= 128;
    const __half* srcp;
    if (!isB) {
        size_t row;
        if (MODE == 0) row = (size_t)tok[lr];
        else { int m = m0 + lr; if (m >= cnt) m = cnt - 1; row = (size_t)(base + m); }
        srcp = ((MODE == 0) ? g_xh : g_h) + row * KTOT;
    } else {
        size_t row = (size_t)e * NROW + n0 + lr;
        srcp = ((MODE == 0) ? g_w1h : g_w2h) + row * KTOT;
    }
    const uint32_t dstbase = S + OFF_TILE + (isB ? OFF_B : 0) + (uint32_t)lr * 128;
    const uint32_t swr = (uint32_t)(lr & 7);

    // ---- fragment addressing ----
    const int lane = tid & 31, wid = tid >> 5;
    const int wm = wid >> 2, wn = wid & 3;          // warp tile: rows wm*64, cols wn*32
    const uint32_t rA   = lane & 15;
    const uint32_t cA   = lane >> 4;                // +0/+1 chunk
    const uint32_t swA  = rA & 7;
    uint32_t rowA[4];
#pragma unroll
    for (int i = 0; i < 4; i++) rowA[i] = (uint32_t)(wm * 64 + i * 16 + rA) * 128;
    const uint32_t rB   = (lane & 7) | ((lane >> 1) & 8);   // +8 for lanes 16..31
    const uint32_t cB   = (lane >> 3) & 1;
    const uint32_t swB  = rB & 7;
    uint32_t rowB[2];
#pragma unroll
    for (int jj = 0; jj < 2; jj++) rowB[jj] = (uint32_t)(wn * 32 + jj * 16 + rB) * 128;

    float C[4][4][4];
#pragma unroll
    for (int i = 0; i < 4; i++)
#pragma unroll
        for (int j = 0; j < 4; j++)
#pragma unroll
            for (int q = 0; q < 4; q++) C[i][j][q] = 0.f;

    LOAD_STAGE(0); CP_COMMIT();
    LOAD_STAGE(1); CP_COMMIT();

    for (int c = 0; c < NCH; c++) {
        CP_WAIT(1);
        __syncthreads();
        // prefetch next stage (buffer (c+2)%3 == (c-1)%3 is free: all warps
        // passed the barrier above, hence finished compute on chunk c-1)
        if (c + 2 < NCH) LOAD_STAGE(c + 2);
        CP_COMMIT();

        const uint32_t aBuf = S + OFF_TILE + (uint32_t)(c % NSTAGE) * STAGE_BYTES;
        const uint32_t bBuf = aBuf + OFF_B;
#pragma unroll
        for (int s = 0; s < 4; s++) {          // 4 x k16 per 64-chunk
            const uint32_t kc = 2 * s;
            uint32_t A[4][4], B[2][4];
#pragma unroll
            for (int i = 0; i < 4; i++)
                ldsm4(A[i], aBuf + rowA[i] + (((kc + cA) ^ swA) << 4));
#pragma unroll
            for (int jj = 0; jj < 2; jj++)
                ldsm4(B[jj], bBuf + rowB[jj] + (((kc + cB) ^ swB) << 4));
#pragma unroll
            for (int i = 0; i < 4; i++)
#pragma unroll
                for (int j = 0; j < 4; j++)
                    mma16816(C[i][j], A[i], &B[j >> 1][(j & 1) * 2]);
        }
    }

    // -------- epilogue --------
    const int gcol0 = n0 + wn * 32;
#pragma unroll
    for (int i = 0; i < 4; i++) {
        const int rbase = wm * 64 + i * 16 + (lane >> 2);
#pragma unroll
        for (int half = 0; half < 2; half++) {
            const int rr = rbase + 8 * half;
            const int m  = m0 + rr;
            if (m >= cnt) continue;
            if (MODE == 0) {
                const size_t pb = (size_t)(base + m) * HH;
#pragma unroll
                for (int j = 0; j < 4; j++) {
                    const int cc = gcol0 + j * 8 + (lane & 3) * 2;
                    float v0 = fmaxf(C[i][j][2 * half]     + bias[e * HH + cc],     0.f);
                    float v1 = fmaxf(C[i][j][2 * half + 1] + bias[e * HH + cc + 1], 0.f);
                    *(__half2*)(&g_h[pb + cc]) = __floats2half2_rn(v0, v1);
                }
            } else {
                const int t = tok[rr];
                const float w = g_topw[t];
                float* op = out + (size_t)t * DD;
#pragma unroll
                for (int j = 0; j < 4; j++) {
                    const int cc = gcol0 + j * 8 + (lane & 3) * 2;
                    float2 v;
                    v.x = w * (C[i][j][2 * half]     + bias[e * DD + cc]);
                    v.y = w * (C[i][j][2 * half + 1] + bias[e * DD + cc + 1]);
                    *(float2*)(op + cc) = v;
                }
            }
        }
    }
}

// -------------------- launch --------------------
extern "C" void kernel_launch(void* const* d_in, const int* in_sizes, int n_in,
                              void* d_out, int out_size) {
    const float* x  = (const float*)d_in[0];
    const float* Wg = (const float*)d_in[1];
    const float* bg = (const float*)d_in[2];
    const float* W1 = (const float*)d_in[3];
    const float* b1 = (const float*)d_in[4];
    const float* W2 = (const float*)d_in[5];
    const float* b2 = (const float*)d_in[6];
    float* out = (float*)d_out;
    float* gw  = out + (size_t)NTOK * DD;   // gate_weights appended after `out`

    cudaFuncSetAttribute(moe_gemm<0>, cudaFuncAttributeMaxDynamicSharedMemorySize, SMEM_TOTAL);
    cudaFuncSetAttribute(moe_gemm<1>, cudaFuncAttributeMaxDynamicSharedMemorySize, SMEM_TOTAL);

    zero_kernel<<<1, 32>>>();                                 // 0
    gate_kernel<<<NTOK / 8, 256>>>(x, Wg, bg, gw);            // 1 (fused x->fp16)
    scan_kernel<<<1, 1>>>();                                  // 2
    scatter_kernel<<<NTOK / 256, 256>>>();                    // 3
    convw_kernel<<<dim3(64, 64, 16), dim3(32, 8)>>>(W1, W2);  // 4
    moe_gemm<0><<<dim3(HH / BN, NTOK / BM, EE), 256, SMEM_TOTAL>>>(b1, nullptr);  // 5
    moe_gemm<1><<<dim3(DD / BN, NTOK / BM, EE), 256, SMEM_TOTAL>>>(b2, out);      // 6
}

// round 6
// speedup vs baseline: 3.3522x; 1.0004x over previous
#include <cuda_runtime.h>
#include <cuda_fp16.h>
#include <math.h>
#include <stdint.h>

// Problem constants
#define NB 8
#define LL 2048
#define NTOK (NB*LL)        // 16384
#define DD 1024
#define EE 8
#define HH 2048

#define BM 128
#define BN 128
#define BK 64
#define NSTAGE 3
#define STAGE_BYTES 32768       // A tile 16KB + B tile 16KB
#define OFF_B 16384
#define OFF_TOK 0
#define OFF_TILE 1024
#define SMEM_TOTAL (OFF_TILE + NSTAGE * STAGE_BYTES)   // 99328

// -------------------- device scratch (no allocs allowed) --------------------
__device__ __half g_xh[(size_t)NTOK * DD];
__device__ __half g_w1h[(size_t)EE * HH * DD];   // [E][H][D]  (W1^T)
__device__ __half g_w2h[(size_t)EE * DD * HH];   // [E][D][H]  (W2^T)
__device__ __half g_h[(size_t)NTOK * HH];        // permuted hidden
__device__ int   g_perm[NTOK];
__device__ int   g_topidx[NTOK];
__device__ float g_topw[NTOK];
__device__ int   g_counts[EE];   // zero at module load; scan re-zeros after use
__device__ int   g_offs[EE + 1];
__device__ int   g_cursor[EE];

// -------------------- PTX helpers (all non-'a' features) --------------------
__device__ __forceinline__ uint32_t smem_u32(const void* p) {
    uint32_t a;
    asm("{ .reg .u64 t; cvta.to.shared.u64 t, %1; cvt.u32.u64 %0, t; }" : "=r"(a) : "l"(p));
    return a;
}
__device__ __forceinline__ void cp16(uint32_t dst, const void* src) {
    asm volatile("cp.async.cg.shared.global [%0], [%1], 16;" :: "r"(dst), "l"(src));
}
#define CP_COMMIT() asm volatile("cp.async.commit_group;" ::: "memory")
#define CP_WAIT(n)  asm volatile("cp.async.wait_group %0;" :: "n"(n) : "memory")

__device__ __forceinline__ void ldsm4(uint32_t* r, uint32_t addr) {
    asm volatile("ldmatrix.sync.aligned.m8n8.x4.shared.b16 {%0,%1,%2,%3}, [%4];"
                 : "=r"(r[0]), "=r"(r[1]), "=r"(r[2]), "=r"(r[3]) : "r"(addr));
}
__device__ __forceinline__ void mma16816(float* c, const uint32_t* a, const uint32_t* b) {
    asm volatile("mma.sync.aligned.m16n8k16.row.col.f32.f16.f16.f32 "
        "{%0,%1,%2,%3}, {%4,%5,%6,%7}, {%8,%9}, {%0,%1,%2,%3};"
        : "+f"(c[0]), "+f"(c[1]), "+f"(c[2]), "+f"(c[3])
        : "r"(a[0]), "r"(a[1]), "r"(a[2]), "r"(a[3]), "r"(b[0]), "r"(b[1]));
}

// -------------------- gating (fused with x->fp16 conversion) --------------------
// counts[] are zero on entry: zero-initialized at module load, and re-zeroed by
// scan_kernel at the end of every previous kernel_launch invocation.
__global__ void gate_kernel(const float* __restrict__ x,
                            const float* __restrict__ Wg,
                            const float* __restrict__ bg,
                            float* __restrict__ gw_out) {
    int warp = threadIdx.x >> 5;
    int lane = threadIdx.x & 31;
    int t = blockIdx.x * 8 + warp;
    if (t >= NTOK) return;

    const float* xr = x + (size_t)t * DD;
    float xv[32];
#pragma unroll
    for (int i = 0; i < 32; i++) xv[i] = xr[lane + 32 * i];

    __half* xh = g_xh + (size_t)t * DD;
#pragma unroll
    for (int i = 0; i < 32; i++) xh[lane + 32 * i] = __float2half_rn(xv[i]);

    float logit[EE];
#pragma unroll
    for (int e = 0; e < EE; e++) {
        float s = 0.f;
#pragma unroll
        for (int i = 0; i < 32; i++) s += xv[i] * Wg[(lane + 32 * i) * EE + e];
#pragma unroll
        for (int o = 16; o > 0; o >>= 1) s += __shfl_xor_sync(0xffffffffu, s, o);
        logit[e] = s + bg[e];
    }

    if (lane == 0) {
        float mx = logit[0]; int bi = 0;
#pragma unroll
        for (int e = 1; e < EE; e++) if (logit[e] > mx) { mx = logit[e]; bi = e; }
        float p[EE]; float se = 0.f;
#pragma unroll
        for (int e = 0; e < EE; e++) { p[e] = expf(logit[e] - mx); se += p[e]; }
        float inv = 1.f / se;
#pragma unroll
        for (int e = 0; e < EE; e++) gw_out[(size_t)t * EE + e] = p[e] * inv;
        g_topidx[t] = bi;
        g_topw[t]  = p[bi] * inv;
        atomicAdd(&g_counts[bi], 1);
    }
}

// -------------------- scan: offsets + cursor, then re-zero counts ------------
__global__ void scan_kernel() {
    int s = 0;
    g_offs[0] = 0;
    for (int e = 0; e < EE; e++) {
        g_cursor[e] = s;
        s += g_counts[e];
        g_offs[e + 1] = s;
        g_counts[e] = 0;          // ready for next kernel_launch invocation
    }
}

// -------------------- prep: fused weight-convert/transpose + scatter ---------
// blocks [0, 65536): convw (z in [0,16), y in [0,64), x in [0,64), 256 threads)
// blocks [65536, 65600): scatter (64 blocks x 256 threads)
__global__ void prep_kernel(const float* __restrict__ W1, const float* __restrict__ W2) {
    const int bid = blockIdx.x;
    const int tid = threadIdx.x;
    if (bid >= 65536) {
        int t = (bid - 65536) * 256 + tid;
        if (t < NTOK) {
            int e = g_topidx[t];
            int pos = atomicAdd(&g_cursor[e], 1);
            g_perm[pos] = t;
        }
        return;
    }
    const int bx = bid & 63, by = (bid >> 6) & 63, bz = bid >> 12;
    const float* src;
    __half* dh;
    int K, N;
    if (bz < EE) {
        src = W1 + (size_t)bz * DD * HH; dh = g_w1h + (size_t)bz * HH * DD;
        K = DD; N = HH;
        if (by >= K / 32) return;
    } else {
        int e = bz - EE;
        src = W2 + (size_t)e * HH * DD; dh = g_w2h + (size_t)e * DD * HH;
        K = HH; N = DD;
        if (bx >= N / 32) return;
    }
    __shared__ float t[32][33];
    const int tx = tid & 31, ty = tid >> 5;
    const int n0 = bx * 32, k0 = by * 32;
#pragma unroll
    for (int i = 0; i < 4; i++)
        t[ty + i * 8][tx] = src[(size_t)(k0 + ty + i * 8) * N + n0 + tx];
    __syncthreads();
#pragma unroll
    for (int i = 0; i < 4; i++) {
        float v = t[tx][ty + i * 8];
        size_t o = (size_t)(n0 + ty + i * 8) * K + (k0 + tx);
        dh[o] = __float2half_rn(v);
    }
}

// -------------------- mma.sync MoE GEMM (fp16, 1-term) --------------------
// SMEM tile row layout (A and B, 128 rows each): 128B/row = 64 fp16 (k-dim),
// 16B chunks swizzled: chunk' = chunk ^ (row & 7)  -> conflict-free ldmatrix + cp.async.
#define LOAD_STAGE(c) do { \
    uint32_t db = dstbase + ((c) % NSTAGE) * STAGE_BYTES; \
    const __half* sp = srcp + (size_t)(c) * BK; \
    cp16(db + ((0u ^ swr) << 4), sp + 0);  cp16(db + ((1u ^ swr) << 4), sp + 8); \
    cp16(db + ((2u ^ swr) << 4), sp + 16); cp16(db + ((3u ^ swr) << 4), sp + 24); \
    cp16(db + ((4u ^ swr) << 4), sp + 32); cp16(db + ((5u ^ swr) << 4), sp + 40); \
    cp16(db + ((6u ^ swr) << 4), sp + 48); cp16(db + ((7u ^ swr) << 4), sp + 56); \
} while (0)

template<int MODE>
__global__ __launch_bounds__(256, 2)
void moe_gemm(const float* __restrict__ bias, float* __restrict__ out) {
    constexpr int KTOT = (MODE == 0) ? DD : HH;
    constexpr int NROW = (MODE == 0) ? HH : DD;
    constexpr int NCH  = KTOT / BK;       // 16 or 32

    const int e    = blockIdx.z;
    const int base = g_offs[e];
    const int cnt  = g_offs[e + 1] - base;
    const int m0   = blockIdx.y * BM;
    if (m0 >= cnt) return;
    const int n0   = blockIdx.x * BN;

    extern __shared__ char smem[];
    const uint32_t S = smem_u32(smem);
    int* tok = (int*)(smem + OFF_TOK);
    const int tid = threadIdx.x;

    if (tid < 128) {
        int m = m0 + tid; if (m >= cnt) m = cnt - 1;
        tok[tid] = g_perm[base + m];
    }
    __syncthreads();

    // ---- async loader setup: tid<128 -> A row tid, tid>=128 -> B row tid-128 ----
    const int lr = tid & 127;
    const bool isB = tid >= 128;
    const __half* srcp;
    if (!isB) {
        size_t row;
        if (MODE == 0) row = (size_t)tok[lr];
        else { int m = m0 + lr; if (m >= cnt) m = cnt - 1; row = (size_t)(base + m); }
        srcp = ((MODE == 0) ? g_xh : g_h) + row * KTOT;
    } else {
        size_t row = (size_t)e * NROW + n0 + lr;
        srcp = ((MODE == 0) ? g_w1h : g_w2h) + row * KTOT;
    }
    const uint32_t dstbase = S + OFF_TILE + (isB ? OFF_B : 0) + (uint32_t)lr * 128;
    const uint32_t swr = (uint32_t)(lr & 7);

    // ---- fragment addressing ----
    const int lane = tid & 31, wid = tid >> 5;
    const int wm = wid >> 2, wn = wid & 3;          // warp tile: rows wm*64, cols wn*32
    const uint32_t rA   = lane & 15;
    const uint32_t cA   = lane >> 4;                // +0/+1 chunk
    const uint32_t swA  = rA & 7;
    uint32_t rowA[4];
#pragma unroll
    for (int i = 0; i < 4; i++) rowA[i] = (uint32_t)(wm * 64 + i * 16 + rA) * 128;
    const uint32_t rB   = (lane & 7) | ((lane >> 1) & 8);   // +8 for lanes 16..31
    const uint32_t cB   = (lane >> 3) & 1;
    const uint32_t swB  = rB & 7;
    uint32_t rowB[2];
#pragma unroll
    for (int jj = 0; jj < 2; jj++) rowB[jj] = (uint32_t)(wn * 32 + jj * 16 + rB) * 128;

    float C[4][4][4];
#pragma unroll
    for (int i = 0; i < 4; i++)
#pragma unroll
        for (int j = 0; j < 4; j++)
#pragma unroll
            for (int q = 0; q < 4; q++) C[i][j][q] = 0.f;

    LOAD_STAGE(0); CP_COMMIT();
    LOAD_STAGE(1); CP_COMMIT();

    for (int c = 0; c < NCH; c++) {
        CP_WAIT(1);
        __syncthreads();
        // prefetch next stage (buffer (c+2)%3 == (c-1)%3 is free: all warps
        // passed the barrier above, hence finished compute on chunk c-1)
        if (c + 2 < NCH) LOAD_STAGE(c + 2);
        CP_COMMIT();

        const uint32_t aBuf = S + OFF_TILE + (uint32_t)(c % NSTAGE) * STAGE_BYTES;
        const uint32_t bBuf = aBuf + OFF_B;
#pragma unroll
        for (int s = 0; s < 4; s++) {          // 4 x k16 per 64-chunk
            const uint32_t kc = 2 * s;
            uint32_t A[4][4], B[2][4];
#pragma unroll
            for (int i = 0; i < 4; i++)
                ldsm4(A[i], aBuf + rowA[i] + (((kc + cA) ^ swA) << 4));
#pragma unroll
            for (int jj = 0; jj < 2; jj++)
                ldsm4(B[jj], bBuf + rowB[jj] + (((kc + cB) ^ swB) << 4));
#pragma unroll
            for (int i = 0; i < 4; i++)
#pragma unroll
                for (int j = 0; j < 4; j++)
                    mma16816(C[i][j], A[i], &B[j >> 1][(j & 1) * 2]);
        }
    }

    // -------- epilogue --------
    const int gcol0 = n0 + wn * 32;
#pragma unroll
    for (int i = 0; i < 4; i++) {
        const int rbase = wm * 64 + i * 16 + (lane >> 2);
#pragma unroll
        for (int half = 0; half < 2; half++) {
            const int rr = rbase + 8 * half;
            const int m  = m0 + rr;
            if (m >= cnt) continue;
            if (MODE == 0) {
                const size_t pb = (size_t)(base + m) * HH;
#pragma unroll
                for (int j = 0; j < 4; j++) {
                    const int cc = gcol0 + j * 8 + (lane & 3) * 2;
                    float v0 = fmaxf(C[i][j][2 * half]     + bias[e * HH + cc],     0.f);
                    float v1 = fmaxf(C[i][j][2 * half + 1] + bias[e * HH + cc + 1], 0.f);
                    *(__half2*)(&g_h[pb + cc]) = __floats2half2_rn(v0, v1);
                }
            } else {
                const int t = tok[rr];
                const float w = g_topw[t];
                float* op = out + (size_t)t * DD;
#pragma unroll
                for (int j = 0; j < 4; j++) {
                    const int cc = gcol0 + j * 8 + (lane & 3) * 2;
                    float2 v;
                    v.x = w * (C[i][j][2 * half]     + bias[e * DD + cc]);
                    v.y = w * (C[i][j][2 * half + 1] + bias[e * DD + cc + 1]);
                    *(float2*)(op + cc) = v;
                }
            }
        }
    }
}

// -------------------- launch --------------------
extern "C" void kernel_launch(void* const* d_in, const int* in_sizes, int n_in,
                              void* d_out, int out_size) {
    const float* x  = (const float*)d_in[0];
    const float* Wg = (const float*)d_in[1];
    const float* bg = (const float*)d_in[2];
    const float* W1 = (const float*)d_in[3];
    const float* b1 = (const float*)d_in[4];
    const float* W2 = (const float*)d_in[5];
    const float* b2 = (const float*)d_in[6];
    float* out = (float*)d_out;
    float* gw  = out + (size_t)NTOK * DD;   // gate_weights appended after `out`

    cudaFuncSetAttribute(moe_gemm<0>, cudaFuncAttributeMaxDynamicSharedMemorySize, SMEM_TOTAL);
    cudaFuncSetAttribute(moe_gemm<1>, cudaFuncAttributeMaxDynamicSharedMemorySize, SMEM_TOTAL);

    gate_kernel<<<NTOK / 8, 256>>>(x, Wg, bg, gw);            // 1 (fused x->fp16 + counts)
    scan_kernel<<<1, 1>>>();                                  // 2 (offs/cursor + re-zero counts)
    prep_kernel<<<65600, 256>>>(W1, W2);                      // 3 (convw + scatter fused)
    moe_gemm<0><<<dim3(HH / BN, NTOK / BM, EE), 256, SMEM_TOTAL>>>(b1, nullptr);  // 4 <- ncu
    moe_gemm<1><<<dim3(DD / BN, NTOK / BM, EE), 256, SMEM_TOTAL>>>(b2, out);      // 5
}

// round 7
// speedup vs baseline: 3.5566x; 1.0610x over previous
#include <cuda_runtime.h>
#include <cuda_fp16.h>
#include <math.h>
#include <stdint.h>

// Problem constants
#define NB 8
#define LL 2048
#define NTOK (NB*LL)        // 16384
#define DD 1024
#define EE 8
#define HH 2048

#define BM 128
#define BN 256
#define BK 64
#define NSTAGE 3
#define ATILE_BYTES 16384       // 128 rows x 128B
#define BTILE_BYTES 32768       // 256 rows x 128B
#define STAGE_BYTES (ATILE_BYTES + BTILE_BYTES)   // 49152
#define OFF_B ATILE_BYTES
#define OFF_TOK 0
#define OFF_TILE 1024
#define SMEM_TOTAL (OFF_TILE + NSTAGE * STAGE_BYTES)   // 148480

// -------------------- device scratch (no allocs allowed) --------------------
__device__ __half g_xh[(size_t)NTOK * DD];
__device__ __half g_w1h[(size_t)EE * HH * DD];   // [E][H][D]  (W1^T)
__device__ __half g_w2h[(size_t)EE * DD * HH];   // [E][D][H]  (W2^T)
__device__ __half g_h[(size_t)NTOK * HH];        // permuted hidden
__device__ int   g_perm[NTOK];
__device__ int   g_topidx[NTOK];
__device__ float g_topw[NTOK];
__device__ int   g_counts[EE];   // zero at module load; scan re-zeros after use
__device__ int   g_offs[EE + 1];
__device__ int   g_cursor[EE];

// -------------------- PTX helpers (all non-'a' features) --------------------
__device__ __forceinline__ uint32_t smem_u32(const void* p) {
    uint32_t a;
    asm("{ .reg .u64 t; cvta.to.shared.u64 t, %1; cvt.u32.u64 %0, t; }" : "=r"(a) : "l"(p));
    return a;
}
__device__ __forceinline__ void cp16(uint32_t dst, const void* src) {
    asm volatile("cp.async.cg.shared.global [%0], [%1], 16;" :: "r"(dst), "l"(src));
}
#define CP_COMMIT() asm volatile("cp.async.commit_group;" ::: "memory")
#define CP_WAIT(n)  asm volatile("cp.async.wait_group %0;" :: "n"(n) : "memory")

__device__ __forceinline__ void ldsm4(uint32_t* r, uint32_t addr) {
    asm volatile("ldmatrix.sync.aligned.m8n8.x4.shared.b16 {%0,%1,%2,%3}, [%4];"
                 : "=r"(r[0]), "=r"(r[1]), "=r"(r[2]), "=r"(r[3]) : "r"(addr));
}
__device__ __forceinline__ void mma16816(float* c, const uint32_t* a, const uint32_t* b) {
    asm volatile("mma.sync.aligned.m16n8k16.row.col.f32.f16.f16.f32 "
        "{%0,%1,%2,%3}, {%4,%5,%6,%7}, {%8,%9}, {%0,%1,%2,%3};"
        : "+f"(c[0]), "+f"(c[1]), "+f"(c[2]), "+f"(c[3])
        : "r"(a[0]), "r"(a[1]), "r"(a[2]), "r"(a[3]), "r"(b[0]), "r"(b[1]));
}

// -------------------- gating (fused with x->fp16 conversion) --------------------
__global__ void gate_kernel(const float* __restrict__ x,
                            const float* __restrict__ Wg,
                            const float* __restrict__ bg,
                            float* __restrict__ gw_out) {
    int warp = threadIdx.x >> 5;
    int lane = threadIdx.x & 31;
    int t = blockIdx.x * 8 + warp;
    if (t >= NTOK) return;

    const float* xr = x + (size_t)t * DD;
    float xv[32];
#pragma unroll
    for (int i = 0; i < 32; i++) xv[i] = xr[lane + 32 * i];

    __half* xh = g_xh + (size_t)t * DD;
#pragma unroll
    for (int i = 0; i < 32; i++) xh[lane + 32 * i] = __float2half_rn(xv[i]);

    float logit[EE];
#pragma unroll
    for (int e = 0; e < EE; e++) {
        float s = 0.f;
#pragma unroll
        for (int i = 0; i < 32; i++) s += xv[i] * Wg[(lane + 32 * i) * EE + e];
#pragma unroll
        for (int o = 16; o > 0; o >>= 1) s += __shfl_xor_sync(0xffffffffu, s, o);
        logit[e] = s + bg[e];
    }

    if (lane == 0) {
        float mx = logit[0]; int bi = 0;
#pragma unroll
        for (int e = 1; e < EE; e++) if (logit[e] > mx) { mx = logit[e]; bi = e; }
        float p[EE]; float se = 0.f;
#pragma unroll
        for (int e = 0; e < EE; e++) { p[e] = expf(logit[e] - mx); se += p[e]; }
        float inv = 1.f / se;
#pragma unroll
        for (int e = 0; e < EE; e++) gw_out[(size_t)t * EE + e] = p[e] * inv;
        g_topidx[t] = bi;
        g_topw[t]  = p[bi] * inv;
        atomicAdd(&g_counts[bi], 1);
    }
}

// -------------------- scan: offsets + cursor, then re-zero counts ------------
__global__ void scan_kernel() {
    int s = 0;
    g_offs[0] = 0;
    for (int e = 0; e < EE; e++) {
        g_cursor[e] = s;
        s += g_counts[e];
        g_offs[e + 1] = s;
        g_counts[e] = 0;          // ready for next kernel_launch invocation
    }
}

// -------------------- prep: fused weight-convert/transpose + scatter ---------
__global__ void prep_kernel(const float* __restrict__ W1, const float* __restrict__ W2) {
    const int bid = blockIdx.x;
    const int tid = threadIdx.x;
    if (bid >= 65536) {
        int t = (bid - 65536) * 256 + tid;
        if (t < NTOK) {
            int e = g_topidx[t];
            int pos = atomicAdd(&g_cursor[e], 1);
            g_perm[pos] = t;
        }
        return;
    }
    const int bx = bid & 63, by = (bid >> 6) & 63, bz = bid >> 12;
    const float* src;
    __half* dh;
    int K, N;
    if (bz < EE) {
        src = W1 + (size_t)bz * DD * HH; dh = g_w1h + (size_t)bz * HH * DD;
        K = DD; N = HH;
        if (by >= K / 32) return;
    } else {
        int e = bz - EE;
        src = W2 + (size_t)e * HH * DD; dh = g_w2h + (size_t)e * DD * HH;
        K = HH; N = DD;
        if (bx >= N / 32) return;
    }
    __shared__ float t[32][33];
    const int tx = tid & 31, ty = tid >> 5;
    const int n0 = bx * 32, k0 = by * 32;
#pragma unroll
    for (int i = 0; i < 4; i++)
        t[ty + i * 8][tx] = src[(size_t)(k0 + ty + i * 8) * N + n0 + tx];
    __syncthreads();
#pragma unroll
    for (int i = 0; i < 4; i++) {
        float v = t[tx][ty + i * 8];
        size_t o = (size_t)(n0 + ty + i * 8) * K + (k0 + tx);
        dh[o] = __float2half_rn(v);
    }
}

// -------------------- mma.sync MoE GEMM (fp16), 128x256 tile, warp 64x64 -----
// SMEM rows 128B = 64 fp16 (k-dim), 16B chunks swizzled by (row&7).
// Loader: thread t row0 = t (A rows 0-127 / B rows 0-127), threads 0-127 also
// load B rows 128-255.
#define LOAD_ROW(ptr, db) do { \
    cp16((db) + ((0u ^ swr) << 4), (ptr) + 0);  cp16((db) + ((1u ^ swr) << 4), (ptr) + 8); \
    cp16((db) + ((2u ^ swr) << 4), (ptr) + 16); cp16((db) + ((3u ^ swr) << 4), (ptr) + 24); \
    cp16((db) + ((4u ^ swr) << 4), (ptr) + 32); cp16((db) + ((5u ^ swr) << 4), (ptr) + 40); \
    cp16((db) + ((6u ^ swr) << 4), (ptr) + 48); cp16((db) + ((7u ^ swr) << 4), (ptr) + 56); \
} while (0)

#define LOAD_STAGE(c) do { \
    uint32_t so = OFF_TILE + ((c) % NSTAGE) * STAGE_BYTES; \
    LOAD_ROW(srcp0 + (size_t)(c) * BK, S + so + dst0); \
    if (tid < 128) LOAD_ROW(srcp1 + (size_t)(c) * BK, S + so + dst1); \
} while (0)

template<int MODE>
__global__ __launch_bounds__(256, 1)
void moe_gemm(const float* __restrict__ bias, float* __restrict__ out) {
    constexpr int KTOT = (MODE == 0) ? DD : HH;
    constexpr int NROW = (MODE == 0) ? HH : DD;
    constexpr int NCH  = KTOT / BK;       // 16 or 32

    const int e    = blockIdx.z;
    const int base = g_offs[e];
    const int cnt  = g_offs[e + 1] - base;
    const int m0   = blockIdx.y * BM;
    if (m0 >= cnt) return;
    const int n0   = blockIdx.x * BN;

    extern __shared__ char smem[];
    const uint32_t S = smem_u32(smem);
    int* tok = (int*)(smem + OFF_TOK);
    const int tid = threadIdx.x;

    if (tid < 128) {
        int m = m0 + tid; if (m >= cnt) m = cnt - 1;
        tok[tid] = g_perm[base + m];
    }
    __syncthreads();

    // ---- loader setup ----
    // row0: tid<128 -> A row tid; tid>=128 -> B row tid-128
    // row1 (tid<128 only): B row 128+tid
    const __half* Abase = (MODE == 0) ? g_xh : g_h;
    const __half* Wbase = (MODE == 0) ? g_w1h : g_w2h;
    const __half* srcp0;
    const __half* srcp1 = nullptr;
    uint32_t dst0, dst1 = 0;
    const uint32_t swr = (uint32_t)(tid & 7);
    if (tid < 128) {
        size_t rowA;
        if (MODE == 0) rowA = (size_t)tok[tid];
        else { int m = m0 + tid; if (m >= cnt) m = cnt - 1; rowA = (size_t)(base + m); }
        srcp0 = Abase + rowA * KTOT;
        dst0  = (uint32_t)tid * 128;                       // A region
        srcp1 = Wbase + ((size_t)e * NROW + n0 + 128 + tid) * KTOT;
        dst1  = OFF_B + (uint32_t)(128 + tid) * 128;       // B rows 128-255
    } else {
        srcp0 = Wbase + ((size_t)e * NROW + n0 + (tid - 128)) * KTOT;
        dst0  = OFF_B + (uint32_t)(tid - 128) * 128;       // B rows 0-127
    }

    // ---- fragment addressing: 8 warps = 2 (M) x 4 (N), warp tile 64x64 ----
    const int lane = tid & 31, wid = tid >> 5;
    const int wm = wid >> 2, wn = wid & 3;
    const uint32_t rA  = lane & 15;
    const uint32_t cA  = lane >> 4;
    const uint32_t swA = rA & 7;
    uint32_t rowA[4];
#pragma unroll
    for (int i = 0; i < 4; i++) rowA[i] = (uint32_t)(wm * 64 + i * 16 + rA) * 128;
    const uint32_t rB  = (lane & 7) | ((lane >> 1) & 8);
    const uint32_t cB  = (lane >> 3) & 1;
    const uint32_t swB = rB & 7;
    uint32_t rowB[4];
#pragma unroll
    for (int jj = 0; jj < 4; jj++) rowB[jj] = OFF_B + (uint32_t)(wn * 64 + jj * 16 + rB) * 128;

    float C[4][8][4];
#pragma unroll
    for (int i = 0; i < 4; i++)
#pragma unroll
        for (int j = 0; j < 8; j++)
#pragma unroll
            for (int q = 0; q < 4; q++) C[i][j][q] = 0.f;

    LOAD_STAGE(0); CP_COMMIT();
    LOAD_STAGE(1); CP_COMMIT();

    for (int c = 0; c < NCH; c++) {
        CP_WAIT(1);
        __syncthreads();
        if (c + 2 < NCH) LOAD_STAGE(c + 2);
        CP_COMMIT();

        const uint32_t buf = S + OFF_TILE + (uint32_t)(c % NSTAGE) * STAGE_BYTES;
#pragma unroll
        for (int s = 0; s < 4; s++) {          // 4 x k16 per 64-chunk
            const uint32_t kc = 2 * s;
            uint32_t A[4][4], B[4][4];
#pragma unroll
            for (int i = 0; i < 4; i++)
                ldsm4(A[i], buf + rowA[i] + (((kc + cA) ^ swA) << 4));
#pragma unroll
            for (int jj = 0; jj < 4; jj++)
                ldsm4(B[jj], buf + rowB[jj] + (((kc + cB) ^ swB) << 4));
#pragma unroll
            for (int i = 0; i < 4; i++)
#pragma unroll
                for (int j = 0; j < 8; j++)
                    mma16816(C[i][j], A[i], &B[j >> 1][(j & 1) * 2]);
        }
    }

    // -------- epilogue --------
    const int gcol0 = n0 + wn * 64;
#pragma unroll
    for (int i = 0; i < 4; i++) {
        const int rbase = wm * 64 + i * 16 + (lane >> 2);
#pragma unroll
        for (int half = 0; half < 2; half++) {
            const int rr = rbase + 8 * half;
            const int m  = m0 + rr;
            if (m >= cnt) continue;
            if (MODE == 0) {
                const size_t pb = (size_t)(base + m) * HH;
#pragma unroll
                for (int j = 0; j < 8; j++) {
                    const int cc = gcol0 + j * 8 + (lane & 3) * 2;
                    float v0 = fmaxf(C[i][j][2 * half]     + bias[e * HH + cc],     0.f);
                    float v1 = fmaxf(C[i][j][2 * half + 1] + bias[e * HH + cc + 1], 0.f);
                    *(__half2*)(&g_h[pb + cc]) = __floats2half2_rn(v0, v1);
                }
            } else {
                const int t = tok[rr];
                const float w = g_topw[t];
                float* op = out + (size_t)t * DD;
#pragma unroll
                for (int j = 0; j < 8; j++) {
                    const int cc = gcol0 + j * 8 + (lane & 3) * 2;
                    float2 v;
                    v.x = w * (C[i][j][2 * half]     + bias[e * DD + cc]);
                    v.y = w * (C[i][j][2 * half + 1] + bias[e * DD + cc + 1]);
                    *(float2*)(op + cc) = v;
                }
            }
        }
    }
}

// -------------------- launch --------------------
extern "C" void kernel_launch(void* const* d_in, const int* in_sizes, int n_in,
                              void* d_out, int out_size) {
    const float* x  = (const float*)d_in[0];
    const float* Wg = (const float*)d_in[1];
    const float* bg = (const float*)d_in[2];
    const float* W1 = (const float*)d_in[3];
    const float* b1 = (const float*)d_in[4];
    const float* W2 = (const float*)d_in[5];
    const float* b2 = (const float*)d_in[6];
    float* out = (float*)d_out;
    float* gw  = out + (size_t)NTOK * DD;   // gate_weights appended after `out`

    cudaFuncSetAttribute(moe_gemm<0>, cudaFuncAttributeMaxDynamicSharedMemorySize, SMEM_TOTAL);
    cudaFuncSetAttribute(moe_gemm<1>, cudaFuncAttributeMaxDynamicSharedMemorySize, SMEM_TOTAL);

    gate_kernel<<<NTOK / 8, 256>>>(x, Wg, bg, gw);            // 1 (fused x->fp16 + counts)
    scan_kernel<<<1, 1>>>();                                  // 2 (offs/cursor + re-zero counts)
    prep_kernel<<<65600, 256>>>(W1, W2);                      // 3 (convw + scatter fused)
    moe_gemm<0><<<dim3(HH / BN, NTOK / BM, EE), 256, SMEM_TOTAL>>>(b1, nullptr);  // 4 <- ncu
    moe_gemm<1><<<dim3(DD / BN, NTOK / BM, EE), 256, SMEM_TOTAL>>>(b2, out);      // 5
}